// round 3
// baseline (speedup 1.0000x reference)
#include <cuda_runtime.h>
#include <cuda_bf16.h>
#include <cstdint>

// ---------------- constants ----------------
#define KP   320           // padded weight K / hidden width (300 -> 320)
#define SH   328           // smem row stride (elems) for H1/H2 tiles
#define BM   128           // edges per block
#define BSTR 40            // Bs smem row stride (elems)
#define NSTG 3             // cp.async pipeline stages

// ---------------- device scratch ----------------
__device__ __align__(16) __nv_bfloat16 g_W1t[384 * 16];   // W1^T padded [n=384][k=16]
__device__ __align__(16) __nv_bfloat16 g_W2t[384 * KP];   // W2^T padded [n=384][k=320]
__device__ __align__(16) __nv_bfloat16 g_W3t[256 * KP];   // W3^T padded [n=256][k=320]
__device__ double g_acc[2];                               // [0]=sum|y-t|, [1]=KL

__device__ __forceinline__ uint32_t smem_u32(const void* p) {
    return (uint32_t)__cvta_generic_to_shared(p);
}

__global__ void k_zero() { g_acc[0] = 0.0; g_acc[1] = 0.0; }

__global__ void k_base(const float* __restrict__ y, const float* __restrict__ tg, int n) {
    __shared__ float red[8];
    float local = 0.f;
    for (int i = blockIdx.x * blockDim.x + threadIdx.x; i < n; i += gridDim.x * blockDim.x)
        local += fabsf(y[i] - tg[i]);
    int lane = threadIdx.x & 31, warp = threadIdx.x >> 5;
    #pragma unroll
    for (int o = 16; o > 0; o >>= 1) local += __shfl_xor_sync(0xffffffffu, local, o);
    if (lane == 0) red[warp] = local;
    __syncthreads();
    if (threadIdx.x < 8) {
        float v = red[threadIdx.x];
        #pragma unroll
        for (int o = 4; o > 0; o >>= 1) v += __shfl_xor_sync(0xffu, v, o);
        if (threadIdx.x == 0) atomicAdd(&g_acc[0], (double)v);
    }
}

__global__ void k_prep_w(const float* __restrict__ W1,
                         const float* __restrict__ W2,
                         const float* __restrict__ W3) {
    int i = blockIdx.x * blockDim.x + threadIdx.x;
    if (i < 384 * 16) {
        int n = i / 16, k = i % 16;
        g_W1t[i] = __float2bfloat16((n < 300 && k < 12) ? W1[k * 300 + n] : 0.f);
    }
    if (i < 384 * KP) {
        int n = i / KP, k = i % KP;
        g_W2t[i] = __float2bfloat16((n < 300 && k < 300) ? W2[k * 300 + n] : 0.f);
    }
    if (i < 256 * KP) {
        int n = i / KP, k = i % KP;
        g_W3t[i] = __float2bfloat16((n < 200 && k < 300) ? W3[k * 200 + n] : 0.f);
    }
}

// ---------------- fully fused edge pipeline (512 threads) ----------------
// smem:
//   H1  : 128*SH bf16        83968 B
//   H2  : 128*SH bf16        83968 B
//   Bs  : NSTG*128*BSTR bf16 30720 B
//   W1s : 384*16 bf16        12288 B
//   Es  : 128*16 bf16         4096 B
//   b1s/b2s 320 f32 each, b3s 256 f32, red 16 f32
#define SMEM_BYTES (83968 + 83968 + 30720 + 12288 + 4096 + 320*4*2 + 256*4 + 64)

__global__ __launch_bounds__(512, 1)
void k_fused(const float* __restrict__ x,
             const int*   __restrict__ ei,
             const float* __restrict__ b1,
             const float* __restrict__ b2,
             const float* __restrict__ b3,
             int nEdges) {
    extern __shared__ __align__(16) char smem_raw[];
    __nv_bfloat16* H1  = (__nv_bfloat16*)smem_raw;
    __nv_bfloat16* H2  = H1 + 128 * SH;
    __nv_bfloat16* Bs  = H2 + 128 * SH;
    __nv_bfloat16* W1s = Bs + NSTG * 128 * BSTR;
    __nv_bfloat16* Es  = W1s + 384 * 16;
    float* b1s = (float*)(Es + 128 * 16);
    float* b2s = b1s + 320;
    float* b3s = b2s + 320;
    float* red = b3s + 256;

    const int t = threadIdx.x;
    const int lane = t & 31, warp = t >> 5;    // 16 warps
    const int mBase = blockIdx.x * BM;
    const int wm = (warp >> 2) * 32;           // 4 warp-rows of 32
    const int wn = (warp & 3) * 32;            // 4 warp-cols of 32
    const int g = lane >> 2, q = lane & 3;

    // ---- stage 0: weights/bias/edge gather into smem ----
    {
        const uint4* src = (const uint4*)g_W1t;
        uint4* dst = (uint4*)W1s;
        for (int i = t; i < 768; i += 512) dst[i] = src[i];
    }
    if (t < 320) {
        b1s[t] = (t < 300) ? b1[t] : 0.f;
        b2s[t] = (t < 300) ? b2[t] : 0.f;
    }
    if (t >= 320 && t < 320 + 256) {
        int i = t - 320;
        b3s[i] = (i < 200) ? b3[i] : 0.f;
    }
    if (t < 256) {
        int el = t >> 1, half = t & 1;
        int e = mBase + el;
        __nv_bfloat16* row = Es + el * 16 + half * 6;
        float v[6] = {0.f, 0.f, 0.f, 0.f, 0.f, 0.f};
        if (e < nEdges) {
            int node = ei[half ? (size_t)nEdges + e : (size_t)e];
            const float* xp = x + (size_t)node * 6;
            float2 a0 = *(const float2*)xp;
            float2 a1 = *(const float2*)(xp + 2);
            float2 a2 = *(const float2*)(xp + 4);
            v[0] = a0.x; v[1] = a0.y; v[2] = a1.x; v[3] = a1.y; v[4] = a2.x; v[5] = a2.y;
        }
        #pragma unroll
        for (int k = 0; k < 6; k++) row[k] = __float2bfloat16(v[k]);
        if (half) {
            *(__nv_bfloat162*)(Es + el * 16 + 12) = __floats2bfloat162_rn(0.f, 0.f);
            *(__nv_bfloat162*)(Es + el * 16 + 14) = __floats2bfloat162_rn(0.f, 0.f);
        }
    }
    __syncthreads();

    float acc[2][4][4];

    // ---- stage 1: GEMM1 (Es[128x16] @ W1t) -> H1, 3 n-passes ----
    {
        uint32_t a[2][4];
        const int arow = wm + (lane & 15);
        const int acol = (lane >> 4) * 8;
        #pragma unroll
        for (int mi = 0; mi < 2; mi++)
            asm volatile("ldmatrix.sync.aligned.m8n8.x4.shared.b16 {%0,%1,%2,%3}, [%4];\n"
                : "=r"(a[mi][0]), "=r"(a[mi][1]), "=r"(a[mi][2]), "=r"(a[mi][3])
                : "r"(smem_u32(Es + (arow + mi * 16) * 16 + acol)));
        #pragma unroll
        for (int p = 0; p < 3; p++) {
            const int n0 = p * 128;
            #pragma unroll
            for (int mi = 0; mi < 2; mi++)
                #pragma unroll
                for (int ni = 0; ni < 4; ni++)
                    #pragma unroll
                    for (int r = 0; r < 4; r++) acc[mi][ni][r] = 0.f;
            uint32_t b[4][2];
            const int brow = n0 + wn + (lane & 7);
            const int bcol = ((lane >> 3) & 1) * 8;
            #pragma unroll
            for (int ni = 0; ni < 4; ni++)
                asm volatile("ldmatrix.sync.aligned.m8n8.x2.shared.b16 {%0,%1}, [%2];\n"
                    : "=r"(b[ni][0]), "=r"(b[ni][1])
                    : "r"(smem_u32(W1s + (brow + ni * 8) * 16 + bcol)));
            #pragma unroll
            for (int mi = 0; mi < 2; mi++)
                #pragma unroll
                for (int ni = 0; ni < 4; ni++)
                    asm volatile("mma.sync.aligned.m16n8k16.row.col.f32.bf16.bf16.f32 "
                        "{%0,%1,%2,%3}, {%4,%5,%6,%7}, {%8,%9}, {%0,%1,%2,%3};\n"
                        : "+f"(acc[mi][ni][0]), "+f"(acc[mi][ni][1]),
                          "+f"(acc[mi][ni][2]), "+f"(acc[mi][ni][3])
                        : "r"(a[mi][0]), "r"(a[mi][1]), "r"(a[mi][2]), "r"(a[mi][3]),
                          "r"(b[ni][0]), "r"(b[ni][1]));
            #pragma unroll
            for (int mi = 0; mi < 2; mi++)
                #pragma unroll
                for (int ni = 0; ni < 4; ni++) {
                    int c0 = n0 + wn + ni * 8 + q * 2;
                    if (c0 >= 320) continue;
                    float bb0 = b1s[c0], bb1 = b1s[c0 + 1];
                    int r0 = wm + mi * 16 + g;
                    *(__nv_bfloat162*)(H1 + r0 * SH + c0) = __floats2bfloat162_rn(
                        fmaxf(acc[mi][ni][0] + bb0, 0.f), fmaxf(acc[mi][ni][1] + bb1, 0.f));
                    *(__nv_bfloat162*)(H1 + (r0 + 8) * SH + c0) = __floats2bfloat162_rn(
                        fmaxf(acc[mi][ni][2] + bb0, 0.f), fmaxf(acc[mi][ni][3] + bb1, 0.f));
                }
        }
    }

    // ---- shared K-loop: acc = Asm[128xKP] @ Bg[n0..n0+127][KP]^T ----
    // 3-stage cp.async ring, ONE __syncthreads per k-chunk.
    auto kloop = [&](const __nv_bfloat16* Asm, const __nv_bfloat16* Bg) {
        #pragma unroll
        for (int mi = 0; mi < 2; mi++)
            #pragma unroll
            for (int ni = 0; ni < 4; ni++)
                #pragma unroll
                for (int r = 0; r < 4; r++) acc[mi][ni][r] = 0.f;
        auto loadB = [&](int buf, int kc) {
            // 128 rows x 32 cols bf16 = 8192 B ; 512 threads x 16 B
            int row = t >> 2, c8 = (t & 3) << 3;
            const __nv_bfloat16* src = Bg + (size_t)row * KP + kc * 32 + c8;
            uint32_t dst = smem_u32(Bs + buf * (128 * BSTR) + row * BSTR + c8);
            asm volatile("cp.async.cg.shared.global [%0], [%1], 16;\n"
                         :: "r"(dst), "l"(src));
        };
        __syncthreads();   // protect Bs reuse across kloops / H-tile publish
        loadB(0, 0);
        asm volatile("cp.async.commit_group;\n");
        loadB(1, 1);
        asm volatile("cp.async.commit_group;\n");
        #pragma unroll 1
        for (int kc = 0; kc < 10; kc++) {
            asm volatile("cp.async.wait_group 1;\n");
            __syncthreads();   // chunk kc ready; all warps done with chunk kc-1
            if (kc + 2 < 10) loadB((kc + 2) % NSTG, kc + 2);
            asm volatile("cp.async.commit_group;\n");   // empty commit keeps count uniform
            const __nv_bfloat16* Bsl = Bs + (kc % NSTG) * (128 * BSTR);
            uint32_t a[2][2][4], b[2][4][2];
            #pragma unroll
            for (int kk = 0; kk < 2; kk++) {
                const int arow = wm + (lane & 15);
                const int acol = kc * 32 + kk * 16 + (lane >> 4) * 8;
                #pragma unroll
                for (int mi = 0; mi < 2; mi++)
                    asm volatile("ldmatrix.sync.aligned.m8n8.x4.shared.b16 {%0,%1,%2,%3}, [%4];\n"
                        : "=r"(a[kk][mi][0]), "=r"(a[kk][mi][1]),
                          "=r"(a[kk][mi][2]), "=r"(a[kk][mi][3])
                        : "r"(smem_u32(Asm + (arow + mi * 16) * SH + acol)));
                const int brow = wn + (lane & 7);
                const int bcol = kk * 16 + ((lane >> 3) & 1) * 8;
                #pragma unroll
                for (int ni = 0; ni < 4; ni++)
                    asm volatile("ldmatrix.sync.aligned.m8n8.x2.shared.b16 {%0,%1}, [%2];\n"
                        : "=r"(b[kk][ni][0]), "=r"(b[kk][ni][1])
                        : "r"(smem_u32(Bsl + (brow + ni * 8) * BSTR + bcol)));
            }
            #pragma unroll
            for (int kk = 0; kk < 2; kk++)
                #pragma unroll
                for (int mi = 0; mi < 2; mi++)
                    #pragma unroll
                    for (int ni = 0; ni < 4; ni++)
                        asm volatile("mma.sync.aligned.m16n8k16.row.col.f32.bf16.bf16.f32 "
                            "{%0,%1,%2,%3}, {%4,%5,%6,%7}, {%8,%9}, {%0,%1,%2,%3};\n"
                            : "+f"(acc[mi][ni][0]), "+f"(acc[mi][ni][1]),
                              "+f"(acc[mi][ni][2]), "+f"(acc[mi][ni][3])
                            : "r"(a[kk][mi][0]), "r"(a[kk][mi][1]),
                              "r"(a[kk][mi][2]), "r"(a[kk][mi][3]),
                              "r"(b[kk][ni][0]), "r"(b[kk][ni][1]));
        }
    };

    // ---- stage 2: GEMM2 (H1 @ W2t) -> H2, 3 n-passes ----
    #pragma unroll 1
    for (int p = 0; p < 3; p++) {
        const int n0 = p * 128;
        kloop(H1, g_W2t + (size_t)n0 * KP);
        __syncthreads();   // all reads of Bs done before epilogue races next kloop? (cheap safety)
        #pragma unroll
        for (int mi = 0; mi < 2; mi++)
            #pragma unroll
            for (int ni = 0; ni < 4; ni++) {
                int c0 = n0 + wn + ni * 8 + q * 2;
                if (c0 >= 320) continue;
                float bb0 = b2s[c0], bb1 = b2s[c0 + 1];
                int r0 = wm + mi * 16 + g;
                *(__nv_bfloat162*)(H2 + r0 * SH + c0) = __floats2bfloat162_rn(
                    fmaxf(acc[mi][ni][0] + bb0, 0.f), fmaxf(acc[mi][ni][1] + bb1, 0.f));
                *(__nv_bfloat162*)(H2 + (r0 + 8) * SH + c0) = __floats2bfloat162_rn(
                    fmaxf(acc[mi][ni][2] + bb0, 0.f), fmaxf(acc[mi][ni][3] + bb1, 0.f));
            }
    }

    // ---- stage 3: GEMM3 (H2 @ W3t), fused KL epilogue, 2 n-passes ----
    float localKL = 0.f;
    #pragma unroll 1
    for (int p = 0; p < 2; p++) {
        const int n0 = p * 128;
        kloop(H2, g_W3t + (size_t)n0 * KP);
        #pragma unroll
        for (int mi = 0; mi < 2; mi++)
            #pragma unroll
            for (int ni = 0; ni < 4; ni++) {
                int c0 = n0 + wn + ni * 8 + q * 2;
                int r0 = mBase + wm + mi * 16 + g;
                #pragma unroll
                for (int h = 0; h < 2; h++) {
                    int r = r0 + h * 8;
                    if (r >= nEdges) continue;
                    #pragma unroll
                    for (int j = 0; j < 2; j++) {
                        int c = c0 + j;
                        if (c >= 200) continue;
                        float v = acc[mi][ni][h * 2 + j] + b3s[c];
                        localKL += (c < 100) ? 0.5f * v * v
                                             : 0.5f * (__expf(v) - v - 1.f);
                    }
                }
            }
    }

    // ---- block reduce + atomic ----
    #pragma unroll
    for (int o = 16; o > 0; o >>= 1) localKL += __shfl_xor_sync(0xffffffffu, localKL, o);
    if (lane == 0) red[warp] = localKL;
    __syncthreads();
    if (t < 16) {
        float v = red[t];
        #pragma unroll
        for (int o = 8; o > 0; o >>= 1) v += __shfl_xor_sync(0xffffu, v, o);
        if (t == 0) atomicAdd(&g_acc[1], (double)v);
    }
}

__global__ void k_finalize(float* out, int nNodes, int nEdges) {
    out[0] = (float)(g_acc[0] / (double)nNodes + g_acc[1] / (double)nEdges);
}

extern "C" void kernel_launch(void* const* d_in, const int* in_sizes, int n_in,
                              void* d_out, int out_size) {
    const float* x   = (const float*)d_in[0];
    const int*   ei  = (const int*)  d_in[1];
    const float* y   = (const float*)d_in[2];
    const float* tgt = (const float*)d_in[3];
    const float* W1  = (const float*)d_in[4];
    const float* b1  = (const float*)d_in[5];
    const float* W2  = (const float*)d_in[6];
    const float* b2  = (const float*)d_in[7];
    const float* W3  = (const float*)d_in[8];
    const float* b3  = (const float*)d_in[9];
    float* out = (float*)d_out;

    const int nNodes = in_sizes[0] / 6;
    const int nEdges = in_sizes[1] / 2;
    const int nY     = in_sizes[2];

    cudaFuncSetAttribute(k_fused, cudaFuncAttributeMaxDynamicSharedMemorySize, SMEM_BYTES);

    k_zero<<<1, 1>>>();
    k_base<<<128, 256>>>(y, tgt, nY);
    k_prep_w<<<(384 * KP + 255) / 256, 256>>>(W1, W2, W3);
    k_fused<<<(nEdges + BM - 1) / BM, 512, SMEM_BYTES>>>(x, ei, b1, b2, b3, nEdges);
    k_finalize<<<1, 1>>>(out, nNodes, nEdges);
}

// round 5
// speedup vs baseline: 1.0707x; 1.0707x over previous
#include <cuda_runtime.h>
#include <cuda_bf16.h>
#include <cstdint>

// ---------------- constants ----------------
#define KP   320           // padded weight K / hidden width (300 -> 320)
#define SH   328           // smem row stride (elems) for H1/H2 tiles
#define BM   128           // edges per block
#define BK   64            // k-elems per pipeline stage
#define BSTR 72            // Bs smem row stride (elems): 144B -> conflict-free LDSM
#define NKC  5             // k chunks per pass (320/64)

// ---------------- device scratch ----------------
__device__ __align__(16) __nv_bfloat16 g_W1t[384 * 16];   // W1^T padded [n=384][k=16]
__device__ __align__(16) __nv_bfloat16 g_W2t[384 * KP];   // W2^T padded [n=384][k=320]
__device__ __align__(16) __nv_bfloat16 g_W3t[256 * KP];   // W3^T padded [n=256][k=320]
__device__ double g_acc[2];                               // [0]=sum|y-t|, [1]=KL

__device__ __forceinline__ uint32_t smem_u32(const void* p) {
    return (uint32_t)__cvta_generic_to_shared(p);
}

__global__ void k_zero() { g_acc[0] = 0.0; g_acc[1] = 0.0; }

__global__ void k_base(const float* __restrict__ y, const float* __restrict__ tg, int n) {
    __shared__ float red[8];
    float local = 0.f;
    for (int i = blockIdx.x * blockDim.x + threadIdx.x; i < n; i += gridDim.x * blockDim.x)
        local += fabsf(y[i] - tg[i]);
    int lane = threadIdx.x & 31, warp = threadIdx.x >> 5;
    #pragma unroll
    for (int o = 16; o > 0; o >>= 1) local += __shfl_xor_sync(0xffffffffu, local, o);
    if (lane == 0) red[warp] = local;
    __syncthreads();
    if (threadIdx.x < 8) {
        float v = red[threadIdx.x];
        #pragma unroll
        for (int o = 4; o > 0; o >>= 1) v += __shfl_xor_sync(0xffu, v, o);
        if (threadIdx.x == 0) atomicAdd(&g_acc[0], (double)v);
    }
}

__global__ void k_prep_w(const float* __restrict__ W1,
                         const float* __restrict__ W2,
                         const float* __restrict__ W3) {
    int i = blockIdx.x * blockDim.x + threadIdx.x;
    if (i < 384 * 16) {
        int n = i / 16, k = i % 16;
        g_W1t[i] = __float2bfloat16((n < 300 && k < 12) ? W1[k * 300 + n] : 0.f);
    }
    if (i < 384 * KP) {
        int n = i / KP, k = i % KP;
        g_W2t[i] = __float2bfloat16((n < 300 && k < 300) ? W2[k * 300 + n] : 0.f);
    }
    if (i < 256 * KP) {
        int n = i / KP, k = i % KP;
        g_W3t[i] = __float2bfloat16((n < 200 && k < 300) ? W3[k * 200 + n] : 0.f);
    }
}

// ---------------- fully fused edge pipeline (256 threads) ----------------
// smem:
//   H1  : 128*SH bf16      83968 B
//   H2  : 128*SH bf16      83968 B
//   Bs  : 2*128*BSTR bf16  36864 B
//   W1s : 384*16 bf16      12288 B
//   Es  : 128*16 bf16       4096 B
//   b1s/b2s 320 f32, b3s 256 f32, red 8 f32
#define SMEM_BYTES (83968 + 83968 + 36864 + 12288 + 4096 + 320*4*2 + 256*4 + 32)

__global__ __launch_bounds__(256, 1)
void k_fused(const float* __restrict__ x,
             const int*   __restrict__ ei,
             const float* __restrict__ b1,
             const float* __restrict__ b2,
             const float* __restrict__ b3,
             int nEdges) {
    extern __shared__ __align__(16) char smem_raw[];
    __nv_bfloat16* H1  = (__nv_bfloat16*)smem_raw;
    __nv_bfloat16* H2  = H1 + 128 * SH;
    __nv_bfloat16* Bs  = H2 + 128 * SH;
    __nv_bfloat16* W1s = Bs + 2 * 128 * BSTR;
    __nv_bfloat16* Es  = W1s + 384 * 16;
    float* b1s = (float*)(Es + 128 * 16);
    float* b2s = b1s + 320;
    float* b3s = b2s + 320;
    float* red = b3s + 256;

    const int t = threadIdx.x;
    const int lane = t & 31, warp = t >> 5;    // 8 warps
    const int mBase = blockIdx.x * BM;
    const int wm = (warp >> 2) * 64;           // 2 warp-rows of 64
    const int wn = (warp & 3) * 32;            // 4 warp-cols of 32
    const int g = lane >> 2, q = lane & 3;

    // ---- stage 0: weights/bias/edge gather into smem ----
    {
        const uint4* src = (const uint4*)g_W1t;
        uint4* dst = (uint4*)W1s;
        for (int i = t; i < 768; i += 256) dst[i] = src[i];
    }
    for (int i = t; i < 320; i += 256) {
        b1s[i] = (i < 300) ? b1[i] : 0.f;
        b2s[i] = (i < 300) ? b2[i] : 0.f;
    }
    if (t < 256) b3s[t] = (t < 200) ? b3[t] : 0.f;
    {
        int el = t >> 1, half = t & 1;
        int e = mBase + el;
        __nv_bfloat16* row = Es + el * 16 + half * 6;
        float v[6] = {0.f, 0.f, 0.f, 0.f, 0.f, 0.f};
        if (e < nEdges) {
            int node = ei[half ? (size_t)nEdges + e : (size_t)e];
            const float* xp = x + (size_t)node * 6;
            float2 a0 = *(const float2*)xp;
            float2 a1 = *(const float2*)(xp + 2);
            float2 a2 = *(const float2*)(xp + 4);
            v[0] = a0.x; v[1] = a0.y; v[2] = a1.x; v[3] = a1.y; v[4] = a2.x; v[5] = a2.y;
        }
        #pragma unroll
        for (int k = 0; k < 6; k++) row[k] = __float2bfloat16(v[k]);
        if (half) {
            *(__nv_bfloat162*)(Es + el * 16 + 12) = __floats2bfloat162_rn(0.f, 0.f);
            *(__nv_bfloat162*)(Es + el * 16 + 14) = __floats2bfloat162_rn(0.f, 0.f);
        }
    }
    __syncthreads();

    float acc[4][4][4];

    // ---- stage 1: GEMM1 (Es[128x16] @ W1t) -> H1, 3 n-passes ----
    {
        uint32_t a[4][4];
        const int arow = wm + (lane & 15);
        const int acol = (lane >> 4) * 8;
        #pragma unroll
        for (int mi = 0; mi < 4; mi++)
            asm volatile("ldmatrix.sync.aligned.m8n8.x4.shared.b16 {%0,%1,%2,%3}, [%4];\n"
                : "=r"(a[mi][0]), "=r"(a[mi][1]), "=r"(a[mi][2]), "=r"(a[mi][3])
                : "r"(smem_u32(Es + (arow + mi * 16) * 16 + acol)));
        #pragma unroll
        for (int p = 0; p < 3; p++) {
            const int n0 = p * 128;
            #pragma unroll
            for (int mi = 0; mi < 4; mi++)
                #pragma unroll
                for (int ni = 0; ni < 4; ni++)
                    #pragma unroll
                    for (int r = 0; r < 4; r++) acc[mi][ni][r] = 0.f;
            uint32_t b[4][2];
            const int brow = n0 + wn + (lane & 7);
            const int bcol = ((lane >> 3) & 1) * 8;
            #pragma unroll
            for (int ni = 0; ni < 4; ni++)
                asm volatile("ldmatrix.sync.aligned.m8n8.x2.shared.b16 {%0,%1}, [%2];\n"
                    : "=r"(b[ni][0]), "=r"(b[ni][1])
                    : "r"(smem_u32(W1s + (brow + ni * 8) * 16 + bcol)));
            #pragma unroll
            for (int mi = 0; mi < 4; mi++)
                #pragma unroll
                for (int ni = 0; ni < 4; ni++)
                    asm volatile("mma.sync.aligned.m16n8k16.row.col.f32.bf16.bf16.f32 "
                        "{%0,%1,%2,%3}, {%4,%5,%6,%7}, {%8,%9}, {%0,%1,%2,%3};\n"
                        : "+f"(acc[mi][ni][0]), "+f"(acc[mi][ni][1]),
                          "+f"(acc[mi][ni][2]), "+f"(acc[mi][ni][3])
                        : "r"(a[mi][0]), "r"(a[mi][1]), "r"(a[mi][2]), "r"(a[mi][3]),
                          "r"(b[ni][0]), "r"(b[ni][1]));
            #pragma unroll
            for (int mi = 0; mi < 4; mi++)
                #pragma unroll
                for (int ni = 0; ni < 4; ni++) {
                    int c0 = n0 + wn + ni * 8 + q * 2;
                    if (c0 >= 320) continue;
                    float bb0 = b1s[c0], bb1 = b1s[c0 + 1];
                    int r0 = wm + mi * 16 + g;
                    *(__nv_bfloat162*)(H1 + r0 * SH + c0) = __floats2bfloat162_rn(
                        fmaxf(acc[mi][ni][0] + bb0, 0.f), fmaxf(acc[mi][ni][1] + bb1, 0.f));
                    *(__nv_bfloat162*)(H1 + (r0 + 8) * SH + c0) = __floats2bfloat162_rn(
                        fmaxf(acc[mi][ni][2] + bb0, 0.f), fmaxf(acc[mi][ni][3] + bb1, 0.f));
                }
        }
    }

    // ---- shared K-loop: acc = Asm[128xKP] @ Bg[n0..n0+127][KP]^T ----
    // BK=64 chunks, 2-stage cp.async ring, ONE __syncthreads per chunk,
    // double-buffered ldmatrix fragments, x4 B loads.
    auto kloop = [&](const __nv_bfloat16* Asm, const __nv_bfloat16* Bg) {
        #pragma unroll
        for (int mi = 0; mi < 4; mi++)
            #pragma unroll
            for (int ni = 0; ni < 4; ni++)
                #pragma unroll
                for (int r = 0; r < 4; r++) acc[mi][ni][r] = 0.f;

        auto loadB = [&](int buf, int kc) {
            // 128 rows x 64 elems (128B) : 8 threads/row x 16B, 4 rounds
            #pragma unroll
            for (int i = 0; i < 4; i++) {
                int row = (t >> 3) + i * 32;
                const __nv_bfloat16* src = Bg + (size_t)row * KP + kc * BK + (t & 7) * 8;
                uint32_t dst = smem_u32(Bs + buf * (128 * BSTR) + row * BSTR + (t & 7) * 8);
                asm volatile("cp.async.cg.shared.global [%0], [%1], 16;\n"
                             :: "r"(dst), "l"(src));
            }
        };
        auto loadFrags = [&](const __nv_bfloat16* Bsl, int kc, int kk,
                             uint32_t (&a)[4][4], uint32_t (&b)[4][2]) {
            const int arow = wm + (lane & 15);
            const int acol = kc * BK + kk * 16 + (lane >> 4) * 8;
            #pragma unroll
            for (int mi = 0; mi < 4; mi++)
                asm volatile("ldmatrix.sync.aligned.m8n8.x4.shared.b16 {%0,%1,%2,%3}, [%4];\n"
                    : "=r"(a[mi][0]), "=r"(a[mi][1]), "=r"(a[mi][2]), "=r"(a[mi][3])
                    : "r"(smem_u32(Asm + (arow + mi * 16) * SH + acol)));
            // B: one x4 per pair of n-tiles: lanes0-15 -> ni=2p (two k-halves),
            // lanes16-31 -> ni=2p+1.
            #pragma unroll
            for (int p = 0; p < 2; p++) {
                const int brow = wn + p * 16 + (lane >> 4) * 8 + (lane & 7);
                const int bcol = kk * 16 + ((lane >> 3) & 1) * 8;
                asm volatile("ldmatrix.sync.aligned.m8n8.x4.shared.b16 {%0,%1,%2,%3}, [%4];\n"
                    : "=r"(b[2 * p][0]), "=r"(b[2 * p][1]),
                      "=r"(b[2 * p + 1][0]), "=r"(b[2 * p + 1][1])
                    : "r"(smem_u32(Bsl + brow * BSTR + bcol)));
            }
        };

        __syncthreads();               // previous consumers of Bs / H writers done
        loadB(0, 0);
        asm volatile("cp.async.commit_group;\n");
        #pragma unroll 1
        for (int kc = 0; kc < NKC; kc++) {
            asm volatile("cp.async.wait_group 0;\n");  // chunk kc resident
            __syncthreads();                            // readers of kc-1 done
            if (kc + 1 < NKC) loadB((kc + 1) & 1, kc + 1);
            asm volatile("cp.async.commit_group;\n");
            const __nv_bfloat16* Bsl = Bs + (kc & 1) * (128 * BSTR);
            uint32_t af[2][4][4], bf[2][4][2];
            loadFrags(Bsl, kc, 0, af[0], bf[0]);
            #pragma unroll
            for (int kk = 0; kk < 4; kk++) {
                if (kk < 3) loadFrags(Bsl, kc, kk + 1, af[(kk + 1) & 1], bf[(kk + 1) & 1]);
                uint32_t (*a)[4] = af[kk & 1];
                uint32_t (*b)[2] = bf[kk & 1];
                #pragma unroll
                for (int mi = 0; mi < 4; mi++)
                    #pragma unroll
                    for (int ni = 0; ni < 4; ni++)
                        asm volatile("mma.sync.aligned.m16n8k16.row.col.f32.bf16.bf16.f32 "
                            "{%0,%1,%2,%3}, {%4,%5,%6,%7}, {%8,%9}, {%0,%1,%2,%3};\n"
                            : "+f"(acc[mi][ni][0]), "+f"(acc[mi][ni][1]),
                              "+f"(acc[mi][ni][2]), "+f"(acc[mi][ni][3])
                            : "r"(a[mi][0]), "r"(a[mi][1]), "r"(a[mi][2]), "r"(a[mi][3]),
                              "r"(b[ni][0]), "r"(b[ni][1]));
            }
        }
    };

    // ---- stage 2: GEMM2 (H1 @ W2t) -> H2, 3 n-passes ----
    #pragma unroll 1
    for (int p = 0; p < 3; p++) {
        const int n0 = p * 128;
        kloop(H1, g_W2t + (size_t)n0 * KP);
        #pragma unroll
        for (int mi = 0; mi < 4; mi++)
            #pragma unroll
            for (int ni = 0; ni < 4; ni++) {
                int c0 = n0 + wn + ni * 8 + q * 2;
                if (c0 >= 320) continue;
                float bb0 = b2s[c0], bb1 = b2s[c0 + 1];
                int r0 = wm + mi * 16 + g;
                *(__nv_bfloat162*)(H2 + r0 * SH + c0) = __floats2bfloat162_rn(
                    fmaxf(acc[mi][ni][0] + bb0, 0.f), fmaxf(acc[mi][ni][1] + bb1, 0.f));
                *(__nv_bfloat162*)(H2 + (r0 + 8) * SH + c0) = __floats2bfloat162_rn(
                    fmaxf(acc[mi][ni][2] + bb0, 0.f), fmaxf(acc[mi][ni][3] + bb1, 0.f));
            }
    }

    // ---- stage 3: GEMM3 (H2 @ W3t), fused KL epilogue, 2 n-passes ----
    float localKL = 0.f;
    #pragma unroll 1
    for (int p = 0; p < 2; p++) {
        const int n0 = p * 128;
        kloop(H2, g_W3t + (size_t)n0 * KP);
        #pragma unroll
        for (int mi = 0; mi < 4; mi++)
            #pragma unroll
            for (int ni = 0; ni < 4; ni++) {
                int c0 = n0 + wn + ni * 8 + q * 2;
                int r0 = mBase + wm + mi * 16 + g;
                #pragma unroll
                for (int h = 0; h < 2; h++) {
                    int r = r0 + h * 8;
                    if (r >= nEdges) continue;
                    #pragma unroll
                    for (int j = 0; j < 2; j++) {
                        int c = c0 + j;
                        if (c >= 200) continue;
                        float v = acc[mi][ni][h * 2 + j] + b3s[c];
                        localKL += (c < 100) ? 0.5f * v * v
                                             : 0.5f * (__expf(v) - v - 1.f);
                    }
                }
            }
    }

    // ---- block reduce + atomic ----
    #pragma unroll
    for (int o = 16; o > 0; o >>= 1) localKL += __shfl_xor_sync(0xffffffffu, localKL, o);
    if (lane == 0) red[warp] = localKL;
    __syncthreads();
    if (t < 8) {
        float v = red[t];
        #pragma unroll
        for (int o = 4; o > 0; o >>= 1) v += __shfl_xor_sync(0xffu, v, o);
        if (t == 0) atomicAdd(&g_acc[1], (double)v);
    }
}

__global__ void k_finalize(float* out, int nNodes, int nEdges) {
    out[0] = (float)(g_acc[0] / (double)nNodes + g_acc[1] / (double)nEdges);
}

extern "C" void kernel_launch(void* const* d_in, const int* in_sizes, int n_in,
                              void* d_out, int out_size) {
    const float* x   = (const float*)d_in[0];
    const int*   ei  = (const int*)  d_in[1];
    const float* y   = (const float*)d_in[2];
    const float* tgt = (const float*)d_in[3];
    const float* W1  = (const float*)d_in[4];
    const float* b1  = (const float*)d_in[5];
    const float* W2  = (const float*)d_in[6];
    const float* b2  = (const float*)d_in[7];
    const float* W3  = (const float*)d_in[8];
    const float* b3  = (const float*)d_in[9];
    float* out = (float*)d_out;

    const int nNodes = in_sizes[0] / 6;
    const int nEdges = in_sizes[1] / 2;
    const int nY     = in_sizes[2];

    cudaFuncSetAttribute(k_fused, cudaFuncAttributeMaxDynamicSharedMemorySize, SMEM_BYTES);

    k_zero<<<1, 1>>>();
    k_base<<<128, 256>>>(y, tgt, nY);
    k_prep_w<<<(384 * KP + 255) / 256, 256>>>(W1, W2, W3);
    k_fused<<<(nEdges + BM - 1) / BM, 256, SMEM_BYTES>>>(x, ei, b1, b2, b3, nEdges);
    k_finalize<<<1, 1>>>(out, nNodes, nEdges);
}

// round 6
// speedup vs baseline: 1.1939x; 1.1151x over previous
#include <cuda_runtime.h>
#include <cuda_bf16.h>
#include <cstdint>

// ---------------- constants ----------------
#define KP   320           // padded weight K / hidden width (300 -> 320)
#define SH   328           // smem row stride (elems) for H1/H2 tiles
#define BM   64            // edges per block (2 CTAs/SM)
#define BK   32            // k-elems per pipeline stage
#define BSTR 40            // Bs smem row stride (elems)
#define NKC  10            // k chunks per pass (320/32)

// ---------------- device scratch ----------------
__device__ __align__(16) __nv_bfloat16 g_W1t[384 * 16];   // W1^T padded [n=384][k=16]
__device__ __align__(16) __nv_bfloat16 g_W2t[384 * KP];   // W2^T padded [n=384][k=320]
__device__ __align__(16) __nv_bfloat16 g_W3t[256 * KP];   // W3^T padded [n=256][k=320]
__device__ double g_acc[2];                               // [0]=sum|y-t|, [1]=KL

__device__ __forceinline__ uint32_t smem_u32(const void* p) {
    return (uint32_t)__cvta_generic_to_shared(p);
}

__global__ void k_zero() { g_acc[0] = 0.0; g_acc[1] = 0.0; }

__global__ void k_base(const float* __restrict__ y, const float* __restrict__ tg, int n) {
    __shared__ float red[8];
    float local = 0.f;
    for (int i = blockIdx.x * blockDim.x + threadIdx.x; i < n; i += gridDim.x * blockDim.x)
        local += fabsf(y[i] - tg[i]);
    int lane = threadIdx.x & 31, warp = threadIdx.x >> 5;
    #pragma unroll
    for (int o = 16; o > 0; o >>= 1) local += __shfl_xor_sync(0xffffffffu, local, o);
    if (lane == 0) red[warp] = local;
    __syncthreads();
    if (threadIdx.x < 8) {
        float v = red[threadIdx.x];
        #pragma unroll
        for (int o = 4; o > 0; o >>= 1) v += __shfl_xor_sync(0xffu, v, o);
        if (threadIdx.x == 0) atomicAdd(&g_acc[0], (double)v);
    }
}

__global__ void k_prep_w(const float* __restrict__ W1,
                         const float* __restrict__ W2,
                         const float* __restrict__ W3) {
    int i = blockIdx.x * blockDim.x + threadIdx.x;
    if (i < 384 * 16) {
        int n = i / 16, k = i % 16;
        g_W1t[i] = __float2bfloat16((n < 300 && k < 12) ? W1[k * 300 + n] : 0.f);
    }
    if (i < 384 * KP) {
        int n = i / KP, k = i % KP;
        g_W2t[i] = __float2bfloat16((n < 300 && k < 300) ? W2[k * 300 + n] : 0.f);
    }
    if (i < 256 * KP) {
        int n = i / KP, k = i % KP;
        g_W3t[i] = __float2bfloat16((n < 200 && k < 300) ? W3[k * 200 + n] : 0.f);
    }
}

// ---------------- fully fused edge pipeline (256 threads, 2 CTAs/SM) ----------------
// smem (dynamic, ~105.6 KB):
//   H1  : 64*SH bf16           41984 B
//   H2  : 64*SH bf16           41984 B
//   Bs  : 2*128*BSTR bf16      20480 B   (also hosts W1s+Es before stage 2)
//   b1s/b2s 320 f32, b3s 256 f32, red 8 f32 : 3616 B
#define OFF_H1   0
#define OFF_H2   (64 * SH)                 // elems
#define OFF_BS   (2 * 64 * SH)             // elems
#define OFF_W1S  OFF_BS                    // union: W1s = first 12288 B of Bs
#define OFF_ES   (OFF_BS + 384 * 16)       // union: Es after W1s (2048 B)
#define ELEMS_BF (2 * 64 * SH + 2 * 128 * BSTR)
#define SMEM_BYTES (ELEMS_BF * 2 + 320*4*2 + 256*4 + 32)

__global__ __launch_bounds__(256, 2)
void k_fused(const float* __restrict__ x,
             const int*   __restrict__ ei,
             const float* __restrict__ b1,
             const float* __restrict__ b2,
             const float* __restrict__ b3,
             int nEdges) {
    extern __shared__ __align__(16) char smem_raw[];
    __nv_bfloat16* base = (__nv_bfloat16*)smem_raw;
    __nv_bfloat16* H1  = base + OFF_H1;
    __nv_bfloat16* H2  = base + OFF_H2;
    __nv_bfloat16* Bs  = base + OFF_BS;
    __nv_bfloat16* W1s = base + OFF_W1S;
    __nv_bfloat16* Es  = base + OFF_ES;
    float* b1s = (float*)(base + ELEMS_BF);
    float* b2s = b1s + 320;
    float* b3s = b2s + 320;
    float* red = b3s + 256;

    const int t = threadIdx.x;
    const int lane = t & 31, warp = t >> 5;    // 8 warps
    const int mBase = blockIdx.x * BM;
    const int wm = (warp >> 2) * 32;           // 2 warp-rows of 32
    const int wn = (warp & 3) * 32;            // 4 warp-cols of 32
    const int g = lane >> 2, q = lane & 3;

    // ---- stage 0: weights/bias/edge gather into smem ----
    {
        const uint4* src = (const uint4*)g_W1t;
        uint4* dst = (uint4*)W1s;
        for (int i = t; i < 768; i += 256) dst[i] = src[i];
    }
    for (int i = t; i < 320; i += 256) {
        b1s[i] = (i < 300) ? b1[i] : 0.f;
        b2s[i] = (i < 300) ? b2[i] : 0.f;
    }
    if (t < 256) b3s[t] = (t < 200) ? b3[t] : 0.f;
    if (t < 128) {
        int el = t >> 1, half = t & 1;
        int e = mBase + el;
        __nv_bfloat16* row = Es + el * 16 + half * 6;
        float v[6] = {0.f, 0.f, 0.f, 0.f, 0.f, 0.f};
        if (e < nEdges) {
            int node = ei[half ? (size_t)nEdges + e : (size_t)e];
            const float* xp = x + (size_t)node * 6;
            float2 a0 = *(const float2*)xp;
            float2 a1 = *(const float2*)(xp + 2);
            float2 a2 = *(const float2*)(xp + 4);
            v[0] = a0.x; v[1] = a0.y; v[2] = a1.x; v[3] = a1.y; v[4] = a2.x; v[5] = a2.y;
        }
        #pragma unroll
        for (int k = 0; k < 6; k++) row[k] = __float2bfloat16(v[k]);
        if (half) {  // zero K-pad cols 12..15
            *(__nv_bfloat162*)(Es + el * 16 + 12) = __floats2bfloat162_rn(0.f, 0.f);
            *(__nv_bfloat162*)(Es + el * 16 + 14) = __floats2bfloat162_rn(0.f, 0.f);
        }
    }
    __syncthreads();

    float acc[2][4][4];

    // ---- stage 1: GEMM1 (Es[64x16] @ W1t) -> H1, 3 n-passes ----
    {
        uint32_t a[2][4];
        const int arow = wm + (lane & 15);
        const int acol = (lane >> 4) * 8;
        #pragma unroll
        for (int mi = 0; mi < 2; mi++)
            asm volatile("ldmatrix.sync.aligned.m8n8.x4.shared.b16 {%0,%1,%2,%3}, [%4];\n"
                : "=r"(a[mi][0]), "=r"(a[mi][1]), "=r"(a[mi][2]), "=r"(a[mi][3])
                : "r"(smem_u32(Es + (arow + mi * 16) * 16 + acol)));
        #pragma unroll
        for (int p = 0; p < 3; p++) {
            const int n0 = p * 128;
            #pragma unroll
            for (int mi = 0; mi < 2; mi++)
                #pragma unroll
                for (int ni = 0; ni < 4; ni++)
                    #pragma unroll
                    for (int r = 0; r < 4; r++) acc[mi][ni][r] = 0.f;
            uint32_t b[4][2];
            const int brow = n0 + wn + (lane & 7);
            const int bcol = ((lane >> 3) & 1) * 8;
            #pragma unroll
            for (int ni = 0; ni < 4; ni++)
                asm volatile("ldmatrix.sync.aligned.m8n8.x2.shared.b16 {%0,%1}, [%2];\n"
                    : "=r"(b[ni][0]), "=r"(b[ni][1])
                    : "r"(smem_u32(W1s + (brow + ni * 8) * 16 + bcol)));
            #pragma unroll
            for (int mi = 0; mi < 2; mi++)
                #pragma unroll
                for (int ni = 0; ni < 4; ni++)
                    asm volatile("mma.sync.aligned.m16n8k16.row.col.f32.bf16.bf16.f32 "
                        "{%0,%1,%2,%3}, {%4,%5,%6,%7}, {%8,%9}, {%0,%1,%2,%3};\n"
                        : "+f"(acc[mi][ni][0]), "+f"(acc[mi][ni][1]),
                          "+f"(acc[mi][ni][2]), "+f"(acc[mi][ni][3])
                        : "r"(a[mi][0]), "r"(a[mi][1]), "r"(a[mi][2]), "r"(a[mi][3]),
                          "r"(b[ni][0]), "r"(b[ni][1]));
            #pragma unroll
            for (int mi = 0; mi < 2; mi++)
                #pragma unroll
                for (int ni = 0; ni < 4; ni++) {
                    int c0 = n0 + wn + ni * 8 + q * 2;
                    if (c0 >= 320) continue;
                    float bb0 = b1s[c0], bb1 = b1s[c0 + 1];
                    int r0 = wm + mi * 16 + g;
                    *(__nv_bfloat162*)(H1 + r0 * SH + c0) = __floats2bfloat162_rn(
                        fmaxf(acc[mi][ni][0] + bb0, 0.f), fmaxf(acc[mi][ni][1] + bb1, 0.f));
                    *(__nv_bfloat162*)(H1 + (r0 + 8) * SH + c0) = __floats2bfloat162_rn(
                        fmaxf(acc[mi][ni][2] + bb0, 0.f), fmaxf(acc[mi][ni][3] + bb1, 0.f));
                }
        }
    }

    // ---- shared K-loop: acc = Asm[64xKP] @ Bg[n0..n0+127][KP]^T ----
    // BK=32, 2-stage cp.async ring, one __syncthreads per chunk.
    auto kloop = [&](const __nv_bfloat16* Asm, const __nv_bfloat16* Bg) {
        #pragma unroll
        for (int mi = 0; mi < 2; mi++)
            #pragma unroll
            for (int ni = 0; ni < 4; ni++)
                #pragma unroll
                for (int r = 0; r < 4; r++) acc[mi][ni][r] = 0.f;

        auto loadB = [&](int buf, int kc) {
            // 128 rows x 32 elems (64B): 4 threads/row x 16B, 2 rounds
            #pragma unroll
            for (int i = 0; i < 2; i++) {
                int row = (t >> 2) + i * 64;
                const __nv_bfloat16* src = Bg + (size_t)row * KP + kc * BK + (t & 3) * 8;
                uint32_t dst = smem_u32(Bs + buf * (128 * BSTR) + row * BSTR + (t & 3) * 8);
                asm volatile("cp.async.cg.shared.global [%0], [%1], 16;\n"
                             :: "r"(dst), "l"(src));
            }
        };

        __syncthreads();               // previous users of Bs region done (incl. W1s/Es)
        loadB(0, 0);
        asm volatile("cp.async.commit_group;\n");
        #pragma unroll 1
        for (int kc = 0; kc < NKC; kc++) {
            asm volatile("cp.async.wait_group 0;\n");  // chunk kc resident
            __syncthreads();                            // all warps past chunk kc-1
            if (kc + 1 < NKC) loadB((kc + 1) & 1, kc + 1);
            asm volatile("cp.async.commit_group;\n");
            const __nv_bfloat16* Bsl = Bs + (kc & 1) * (128 * BSTR);
            #pragma unroll
            for (int kk = 0; kk < 2; kk++) {
                uint32_t a[2][4], b[4][2];
                const int arow = wm + (lane & 15);
                const int acol = kc * BK + kk * 16 + (lane >> 4) * 8;
                #pragma unroll
                for (int mi = 0; mi < 2; mi++)
                    asm volatile("ldmatrix.sync.aligned.m8n8.x4.shared.b16 {%0,%1,%2,%3}, [%4];\n"
                        : "=r"(a[mi][0]), "=r"(a[mi][1]), "=r"(a[mi][2]), "=r"(a[mi][3])
                        : "r"(smem_u32(Asm + (arow + mi * 16) * SH + acol)));
                const int brow = wn + (lane & 7);
                const int bcol = kk * 16 + ((lane >> 3) & 1) * 8;
                #pragma unroll
                for (int ni = 0; ni < 4; ni++)
                    asm volatile("ldmatrix.sync.aligned.m8n8.x2.shared.b16 {%0,%1}, [%2];\n"
                        : "=r"(b[ni][0]), "=r"(b[ni][1])
                        : "r"(smem_u32(Bsl + (brow + ni * 8) * BSTR + bcol)));
                #pragma unroll
                for (int mi = 0; mi < 2; mi++)
                    #pragma unroll
                    for (int ni = 0; ni < 4; ni++)
                        asm volatile("mma.sync.aligned.m16n8k16.row.col.f32.bf16.bf16.f32 "
                            "{%0,%1,%2,%3}, {%4,%5,%6,%7}, {%8,%9}, {%0,%1,%2,%3};\n"
                            : "+f"(acc[mi][ni][0]), "+f"(acc[mi][ni][1]),
                              "+f"(acc[mi][ni][2]), "+f"(acc[mi][ni][3])
                            : "r"(a[mi][0]), "r"(a[mi][1]), "r"(a[mi][2]), "r"(a[mi][3]),
                              "r"(b[ni][0]), "r"(b[ni][1]));
            }
        }
    };

    // ---- stage 2: GEMM2 (H1 @ W2t) -> H2, 3 n-passes ----
    #pragma unroll 1
    for (int p = 0; p < 3; p++) {
        const int n0 = p * 128;
        kloop(H1, g_W2t + (size_t)n0 * KP);
        #pragma unroll
        for (int mi = 0; mi < 2; mi++)
            #pragma unroll
            for (int ni = 0; ni < 4; ni++) {
                int c0 = n0 + wn + ni * 8 + q * 2;
                if (c0 >= 320) continue;
                float bb0 = b2s[c0], bb1 = b2s[c0 + 1];
                int r0 = wm + mi * 16 + g;
                *(__nv_bfloat162*)(H2 + r0 * SH + c0) = __floats2bfloat162_rn(
                    fmaxf(acc[mi][ni][0] + bb0, 0.f), fmaxf(acc[mi][ni][1] + bb1, 0.f));
                *(__nv_bfloat162*)(H2 + (r0 + 8) * SH + c0) = __floats2bfloat162_rn(
                    fmaxf(acc[mi][ni][2] + bb0, 0.f), fmaxf(acc[mi][ni][3] + bb1, 0.f));
            }
    }

    // ---- stage 3: GEMM3 (H2 @ W3t), fused KL epilogue, 2 n-passes ----
    float localKL = 0.f;
    #pragma unroll 1
    for (int p = 0; p < 2; p++) {
        const int n0 = p * 128;
        kloop(H2, g_W3t + (size_t)n0 * KP);
        #pragma unroll
        for (int mi = 0; mi < 2; mi++)
            #pragma unroll
            for (int ni = 0; ni < 4; ni++) {
                int c0 = n0 + wn + ni * 8 + q * 2;
                int r0 = mBase + wm + mi * 16 + g;
                #pragma unroll
                for (int h = 0; h < 2; h++) {
                    int r = r0 + h * 8;
                    if (r >= nEdges) continue;
                    #pragma unroll
                    for (int j = 0; j < 2; j++) {
                        int c = c0 + j;
                        if (c >= 200) continue;
                        float v = acc[mi][ni][h * 2 + j] + b3s[c];
                        localKL += (c < 100) ? 0.5f * v * v
                                             : 0.5f * (__expf(v) - v - 1.f);
                    }
                }
            }
    }

    // ---- block reduce + atomic ----
    #pragma unroll
    for (int o = 16; o > 0; o >>= 1) localKL += __shfl_xor_sync(0xffffffffu, localKL, o);
    if (lane == 0) red[warp] = localKL;
    __syncthreads();
    if (t < 8) {
        float v = red[t];
        #pragma unroll
        for (int o = 4; o > 0; o >>= 1) v += __shfl_xor_sync(0xffu, v, o);
        if (t == 0) atomicAdd(&g_acc[1], (double)v);
    }
}

__global__ void k_finalize(float* out, int nNodes, int nEdges) {
    out[0] = (float)(g_acc[0] / (double)nNodes + g_acc[1] / (double)nEdges);
}

extern "C" void kernel_launch(void* const* d_in, const int* in_sizes, int n_in,
                              void* d_out, int out_size) {
    const float* x   = (const float*)d_in[0];
    const int*   ei  = (const int*)  d_in[1];
    const float* y   = (const float*)d_in[2];
    const float* tgt = (const float*)d_in[3];
    const float* W1  = (const float*)d_in[4];
    const float* b1  = (const float*)d_in[5];
    const float* W2  = (const float*)d_in[6];
    const float* b2  = (const float*)d_in[7];
    const float* W3  = (const float*)d_in[8];
    const float* b3  = (const float*)d_in[9];
    float* out = (float*)d_out;

    const int nNodes = in_sizes[0] / 6;
    const int nEdges = in_sizes[1] / 2;
    const int nY     = in_sizes[2];

    cudaFuncSetAttribute(k_fused, cudaFuncAttributeMaxDynamicSharedMemorySize, SMEM_BYTES);

    k_zero<<<1, 1>>>();
    k_base<<<128, 256>>>(y, tgt, nY);
    k_prep_w<<<(384 * KP + 255) / 256, 256>>>(W1, W2, W3);
    k_fused<<<(nEdges + BM - 1) / BM, 256, SMEM_BYTES>>>(x, ei, b1, b2, b3, nEdges);
    k_finalize<<<1, 1>>>(out, nNodes, nEdges);
}